// round 5
// baseline (speedup 1.0000x reference)
#include <cuda_runtime.h>

#define N_USR 50000
#define N_ENT 100000
#define DD 64
#define NE 1000000
#define NEI 500000

// ---- scratch (device globals; no allocation allowed) ----
__device__ __align__(16) float    g_P[N_ENT * DD];      // E @ W_Q
__device__ __align__(16) float    g_ecur[N_ENT * DD];   // current entity emb
__device__ __align__(16) float    g_esum[N_ENT * DD];   // running sum of entity embs
__device__ __align__(16) float    g_agg[N_ENT * DD];    // scatter accumulator
__device__ __align__(16) float2   g_score[NE];          // per-edge per-head scores
__device__ __align__(16) unsigned g_m[N_ENT * 2];       // encoded segment max
__device__ __align__(16) float    g_den[N_ENT * 2];     // softmax denominators

// order-preserving float <-> uint encoding (so atomicMax(unsigned) works; 0 == "-inf")
__device__ __forceinline__ unsigned f2o(float f) {
    unsigned u = __float_as_uint(f);
    return (u & 0x80000000u) ? ~u : (u | 0x80000000u);
}
__device__ __forceinline__ float o2f(unsigned u) {
    return __uint_as_float((u & 0x80000000u) ? (u & 0x7fffffffu) : ~u);
}

// ---- init: ecur = esum = entity_emb; d_out user region = user_emb;
//      zero layer-0 accumulators (agg, m, den) ----
__global__ void k_init(const float4* __restrict__ ue, const float4* __restrict__ ee,
                       float4* __restrict__ uout) {
    int i = blockIdx.x * blockDim.x + threadIdx.x;
    if (i < N_ENT * DD / 4) {
        float4 v = ee[i];
        ((float4*)g_ecur)[i] = v;
        ((float4*)g_esum)[i] = v;
        ((float4*)g_agg)[i] = make_float4(0.f, 0.f, 0.f, 0.f);
    }
    if (i < N_USR * DD / 4) uout[i] = ue[i];
    if (i < N_ENT * 2 / 4) {
        ((uint4*)g_m)[i] = make_uint4(0u, 0u, 0u, 0u);
        ((float4*)g_den)[i] = make_float4(0.f, 0.f, 0.f, 0.f);
    }
}

// ---- P = g_ecur @ W_Q ; warp handles 4 rows, lane owns 2 output cols ----
__global__ void k_gemm(const float* __restrict__ W) {
    __shared__ float sW[DD * DD];
    for (int i = threadIdx.x; i < DD * DD; i += 256) sW[i] = W[i];
    __syncthreads();
    int warp = threadIdx.x >> 5, lane = threadIdx.x & 31;
    int r0 = (blockIdx.x * 8 + warp) * 4;   // N_ENT % 32 == 0: always full
    if (r0 >= N_ENT) return;
    const float* e0 = &g_ecur[(size_t)r0 * DD];
    float acc[8] = {0.f, 0.f, 0.f, 0.f, 0.f, 0.f, 0.f, 0.f};
    #pragma unroll 4
    for (int k = 0; k < DD; k += 4) {
        float4 a[4];
        #pragma unroll
        for (int rr = 0; rr < 4; rr++) a[rr] = *(const float4*)&e0[rr * DD + k];
        #pragma unroll
        for (int j = 0; j < 4; j++) {
            float2 w = *(const float2*)&sW[(k + j) * DD + lane * 2];
            #pragma unroll
            for (int rr = 0; rr < 4; rr++) {
                float av = (j == 0) ? a[rr].x : (j == 1) ? a[rr].y : (j == 2) ? a[rr].z : a[rr].w;
                acc[rr * 2]     += av * w.x;
                acc[rr * 2 + 1] += av * w.y;
            }
        }
    }
    #pragma unroll
    for (int rr = 0; rr < 4; rr++)
        *(float2*)&g_P[(size_t)(r0 + rr) * DD + lane * 2] =
            make_float2(acc[rr * 2], acc[rr * 2 + 1]);
}

// ---- per-edge score + segment max (16 lanes per edge) ----
__global__ void k_score(const int* __restrict__ head, const int* __restrict__ tail,
                        const int* __restrict__ et, const float* __restrict__ rel) {
    int gid = blockIdx.x * blockDim.x + threadIdx.x;
    int e = gid >> 4, lane = gid & 15;
    if (e >= NE) return;
    int h = __ldg(&head[e]), t = __ldg(&tail[e]), r = __ldg(&et[e]) - 1;
    float4 ph = *(const float4*)&g_P[(size_t)h * DD + lane * 4];
    float4 pt = *(const float4*)&g_P[(size_t)t * DD + lane * 4];
    float4 rl = __ldg((const float4*)&rel[r * DD + lane * 4]);
    float p = ph.x * pt.x * rl.x + ph.y * pt.y * rl.y +
              ph.z * pt.z * rl.z + ph.w * pt.w * rl.w;
    p += __shfl_xor_sync(0xffffffffu, p, 1);
    p += __shfl_xor_sync(0xffffffffu, p, 2);
    p += __shfl_xor_sync(0xffffffffu, p, 4);
    const float inv = 0.17677669529663688f;  // 1/sqrt(32)
    if (lane == 0) {
        float s = p * inv;
        g_score[e].x = s;
        atomicMax(&g_m[h * 2 + 0], f2o(s));
    } else if (lane == 8) {
        float s = p * inv;
        g_score[e].y = s;
        atomicMax(&g_m[h * 2 + 1], f2o(s));
    }
}

// ---- softmax denominators ----
__global__ void k_den(const int* __restrict__ head) {
    int e = blockIdx.x * blockDim.x + threadIdx.x;
    if (e >= NE) return;
    int h = __ldg(&head[e]);
    float2 s = g_score[e];
    float m0 = o2f(g_m[h * 2]), m1 = o2f(g_m[h * 2 + 1]);
    atomicAdd(&g_den[h * 2],     __expf(s.x - m0));
    atomicAdd(&g_den[h * 2 + 1], __expf(s.y - m1));
}

// ---- user aggregation: uout += w * ecur[item]  (16 lanes per inter-edge) ----
__global__ void k_user(const int* __restrict__ iu, const int* __restrict__ ii,
                       const float* __restrict__ w, float* __restrict__ uout) {
    int gid = blockIdx.x * blockDim.x + threadIdx.x;
    int e = gid >> 4, lane = gid & 15;
    if (e >= NEI) return;
    int u = __ldg(&iu[e]), it = __ldg(&ii[e]);
    float ww = __ldg(&w[e]);
    float4 v = *(const float4*)&g_ecur[(size_t)it * DD + lane * 4];
    atomicAdd((float4*)&uout[(size_t)u * DD + lane * 4],
              make_float4(v.x * ww, v.y * ww, v.z * ww, v.w * ww));
}

// ---- scatter value*attn into agg (16 lanes per edge, float4 vector atomics) ----
__global__ void k_scatter(const int* __restrict__ head, const int* __restrict__ tail,
                          const int* __restrict__ et, const float* __restrict__ rel) {
    int gid = blockIdx.x * blockDim.x + threadIdx.x;
    int e = gid >> 4, lane = gid & 15;
    if (e >= NE) return;
    int h = __ldg(&head[e]), t = __ldg(&tail[e]), r = __ldg(&et[e]) - 1;
    float2 s = g_score[e];
    float a;
    if (lane < 8) {
        float m0 = o2f(g_m[h * 2]);
        a = __expf(s.x - m0) / g_den[h * 2];
    } else {
        float m1 = o2f(g_m[h * 2 + 1]);
        a = __expf(s.y - m1) / g_den[h * 2 + 1];
    }
    float4 v  = *(const float4*)&g_ecur[(size_t)t * DD + lane * 4];
    float4 rl = __ldg((const float4*)&rel[r * DD + lane * 4]);
    float4 o  = make_float4(v.x * rl.x * a, v.y * rl.y * a, v.z * rl.z * a, v.w * rl.w * a);
    atomicAdd((float4*)&g_agg[(size_t)h * DD + lane * 4], o);
}

// ---- entity update: L2 normalize agg -> ecur, esum += ecur;
//      re-zero agg/m/den for the next layer ----
__global__ void k_update() {
    int gid = blockIdx.x * blockDim.x + threadIdx.x;
    int row = gid >> 4, lane = gid & 15;
    if (row >= N_ENT) return;
    float4* ap = (float4*)&g_agg[(size_t)row * DD + lane * 4];
    float4 a = *ap;
    *ap = make_float4(0.f, 0.f, 0.f, 0.f);           // ready for next layer
    if (lane < 2) {
        g_m[row * 2 + lane] = 0u;
        g_den[row * 2 + lane] = 0.f;
    }
    float ss = a.x * a.x + a.y * a.y + a.z * a.z + a.w * a.w;
    ss += __shfl_xor_sync(0xffffffffu, ss, 1);
    ss += __shfl_xor_sync(0xffffffffu, ss, 2);
    ss += __shfl_xor_sync(0xffffffffu, ss, 4);
    ss += __shfl_xor_sync(0xffffffffu, ss, 8);
    float inv = 1.f / fmaxf(sqrtf(ss), 1e-12f);
    float4 en = make_float4(a.x * inv, a.y * inv, a.z * inv, a.w * inv);
    *(float4*)&g_ecur[(size_t)row * DD + lane * 4] = en;
    float4* es = (float4*)&g_esum[(size_t)row * DD + lane * 4];
    float4 o = *es;
    *es = make_float4(o.x + en.x, o.y + en.y, o.z + en.z, o.w + en.w);
}

// ---- final: scale user sums, write entity means ----
__global__ void k_final(float* __restrict__ out) {
    int i = blockIdx.x * blockDim.x + threadIdx.x;
    const float th = 1.f / 3.f;
    if (i < N_ENT * DD / 4) {
        float4 v = ((float4*)g_esum)[i];
        float4* oe = (float4*)(out + (size_t)N_USR * DD);
        oe[i] = make_float4(v.x * th, v.y * th, v.z * th, v.w * th);
    }
    if (i < N_USR * DD / 4) {
        float4* uo = (float4*)out;
        float4 v = uo[i];
        uo[i] = make_float4(v.x * th, v.y * th, v.z * th, v.w * th);
    }
}

extern "C" void kernel_launch(void* const* d_in, const int* in_sizes, int n_in,
                              void* d_out, int out_size) {
    // inputs (metadata order): layers_num, user_emb, entity_emb, inter_edge,
    // inter_edge_w, edge_index, edge_type, relation_emb, W_Q
    const float* user_emb = (const float*)d_in[1];
    const float* ent_emb  = (const float*)d_in[2];
    const int*   inter    = (const int*)d_in[3];
    const float* iw       = (const float*)d_in[4];
    const int*   eidx     = (const int*)d_in[5];
    const int*   etype    = (const int*)d_in[6];
    const float* rel      = (const float*)d_in[7];
    const float* WQ       = (const float*)d_in[8];
    const int* head = eidx;
    const int* tail = eidx + NE;
    const int* iu = inter;
    const int* ii = inter + NEI;
    float* out = (float*)d_out;

    const int T = 256;
    const int nE4 = N_ENT * DD / 4;  // 1.6M

    k_init<<<(nE4 + T - 1) / T, T>>>((const float4*)user_emb, (const float4*)ent_emb,
                                     (float4*)out);
    for (int l = 0; l < 2; l++) {
        k_gemm<<<N_ENT / 32, 256>>>(WQ);
        k_score<<<(NE * 16 + T - 1) / T, T>>>(head, tail, etype, rel);
        k_den<<<(NE + T - 1) / T, T>>>(head);
        k_user<<<(NEI * 16 + T - 1) / T, T>>>(iu, ii, iw, out);   // uses pre-update ecur
        k_scatter<<<(NE * 16 + T - 1) / T, T>>>(head, tail, etype, rel);
        k_update<<<(N_ENT * 16 + T - 1) / T, T>>>();
    }
    k_final<<<(nE4 + T - 1) / T, T>>>(out);
}

// round 6
// speedup vs baseline: 1.1649x; 1.1649x over previous
#include <cuda_runtime.h>

#define N_USR 50000
#define N_ENT 100000
#define DD 64
#define NE 1000000
#define NEI 500000

// ---- scratch (device globals; no allocation allowed) ----
__device__ __align__(16) float g_P[N_ENT * DD];      // E @ W_Q
__device__ __align__(16) float g_ecur[N_ENT * DD];   // current entity emb
__device__ __align__(16) float g_esum[N_ENT * DD];   // running sum of entity embs
__device__ __align__(16) float g_agg[N_ENT * DD];    // unnormalized scatter accumulator
__device__ __align__(16) float g_den[N_ENT * 2];     // softmax denominators (per head)

// ---- init: ecur = esum = entity_emb; d_out user region = user_emb;
//      zero layer-0 accumulators (agg, den) ----
__global__ void k_init(const float4* __restrict__ ue, const float4* __restrict__ ee,
                       float4* __restrict__ uout) {
    int i = blockIdx.x * blockDim.x + threadIdx.x;
    if (i < N_ENT * DD / 4) {
        float4 v = ee[i];
        ((float4*)g_ecur)[i] = v;
        ((float4*)g_esum)[i] = v;
        ((float4*)g_agg)[i] = make_float4(0.f, 0.f, 0.f, 0.f);
    }
    if (i < N_USR * DD / 4) uout[i] = ue[i];
    if (i < N_ENT * 2 / 4)
        ((float4*)g_den)[i] = make_float4(0.f, 0.f, 0.f, 0.f);
}

// ---- P = g_ecur @ W_Q ; warp handles 4 rows, lane owns 2 output cols ----
__global__ void k_gemm(const float* __restrict__ W) {
    __shared__ float sW[DD * DD];
    for (int i = threadIdx.x; i < DD * DD; i += 256) sW[i] = W[i];
    __syncthreads();
    int warp = threadIdx.x >> 5, lane = threadIdx.x & 31;
    int r0 = (blockIdx.x * 8 + warp) * 4;   // N_ENT % 32 == 0: always full
    if (r0 >= N_ENT) return;
    const float* e0 = &g_ecur[(size_t)r0 * DD];
    float acc[8] = {0.f, 0.f, 0.f, 0.f, 0.f, 0.f, 0.f, 0.f};
    #pragma unroll 4
    for (int k = 0; k < DD; k += 4) {
        float4 a[4];
        #pragma unroll
        for (int rr = 0; rr < 4; rr++) a[rr] = *(const float4*)&e0[rr * DD + k];
        #pragma unroll
        for (int j = 0; j < 4; j++) {
            float2 w = *(const float2*)&sW[(k + j) * DD + lane * 2];
            #pragma unroll
            for (int rr = 0; rr < 4; rr++) {
                float av = (j == 0) ? a[rr].x : (j == 1) ? a[rr].y : (j == 2) ? a[rr].z : a[rr].w;
                acc[rr * 2]     += av * w.x;
                acc[rr * 2 + 1] += av * w.y;
            }
        }
    }
    #pragma unroll
    for (int rr = 0; rr < 4; rr++)
        *(float2*)&g_P[(size_t)(r0 + rr) * DD + lane * 2] =
            make_float2(acc[rr * 2], acc[rr * 2 + 1]);
}

// ---- FUSED edge pass: score -> ex=exp(score) -> den += ex ; agg += ex*(v*rel)
//      (division by den deferred to k_update; max-subtraction dropped: scores
//       are O(1), exp(s)/sum(exp(s)) is numerically identical at f32)
//      16 lanes per edge: lanes 0-7 = head 0 (dims 0-31), 8-15 = head 1 ----
__global__ void k_edge(const int* __restrict__ head, const int* __restrict__ tail,
                       const int* __restrict__ et, const float* __restrict__ rel) {
    int gid = blockIdx.x * blockDim.x + threadIdx.x;
    int e = gid >> 4, lane = gid & 15;
    if (e >= NE) return;
    int h = __ldg(&head[e]), t = __ldg(&tail[e]), r = __ldg(&et[e]) - 1;
    float4 ph = *(const float4*)&g_P[(size_t)h * DD + lane * 4];
    float4 pt = *(const float4*)&g_P[(size_t)t * DD + lane * 4];
    float4 rl = __ldg((const float4*)&rel[r * DD + lane * 4]);
    float4 key = make_float4(pt.x * rl.x, pt.y * rl.y, pt.z * rl.z, pt.w * rl.w);
    float p = ph.x * key.x + ph.y * key.y + ph.z * key.z + ph.w * key.w;
    // reduce across the 8 lanes of this head (xor masks stay within 8-lane groups)
    p += __shfl_xor_sync(0xffffffffu, p, 1);
    p += __shfl_xor_sync(0xffffffffu, p, 2);
    p += __shfl_xor_sync(0xffffffffu, p, 4);
    const float inv = 0.17677669529663688f;  // 1/sqrt(32)
    float ex = __expf(p * inv);
    if ((lane & 7) == 0)
        atomicAdd(&g_den[h * 2 + (lane >> 3)], ex);
    float4 v = *(const float4*)&g_ecur[(size_t)t * DD + lane * 4];
    float4 o = make_float4(v.x * rl.x * ex, v.y * rl.y * ex,
                           v.z * rl.z * ex, v.w * rl.w * ex);
    atomicAdd((float4*)&g_agg[(size_t)h * DD + lane * 4], o);
}

// ---- user aggregation: uout += w * ecur[item]  (16 lanes per inter-edge) ----
__global__ void k_user(const int* __restrict__ iu, const int* __restrict__ ii,
                       const float* __restrict__ w, float* __restrict__ uout) {
    int gid = blockIdx.x * blockDim.x + threadIdx.x;
    int e = gid >> 4, lane = gid & 15;
    if (e >= NEI) return;
    int u = __ldg(&iu[e]), it = __ldg(&ii[e]);
    float ww = __ldg(&w[e]);
    float4 v = *(const float4*)&g_ecur[(size_t)it * DD + lane * 4];
    atomicAdd((float4*)&uout[(size_t)u * DD + lane * 4],
              make_float4(v.x * ww, v.y * ww, v.z * ww, v.w * ww));
}

// ---- entity update: agg/den per head -> L2 normalize -> ecur, esum += ecur;
//      re-zero agg/den for the next layer ----
__global__ void k_update() {
    int gid = blockIdx.x * blockDim.x + threadIdx.x;
    int row = gid >> 4, lane = gid & 15;
    if (row >= N_ENT) return;
    float4* ap = (float4*)&g_agg[(size_t)row * DD + lane * 4];
    float4 a = *ap;
    *ap = make_float4(0.f, 0.f, 0.f, 0.f);           // ready for next layer
    float d = g_den[row * 2 + (lane >> 3)];
    float invd = (d > 0.f) ? (1.f / d) : 0.f;        // no-edge rows stay 0
    if (lane < 2) g_den[row * 2 + lane] = 0.f;
    a = make_float4(a.x * invd, a.y * invd, a.z * invd, a.w * invd);
    float ss = a.x * a.x + a.y * a.y + a.z * a.z + a.w * a.w;
    ss += __shfl_xor_sync(0xffffffffu, ss, 1);
    ss += __shfl_xor_sync(0xffffffffu, ss, 2);
    ss += __shfl_xor_sync(0xffffffffu, ss, 4);
    ss += __shfl_xor_sync(0xffffffffu, ss, 8);
    float inv = 1.f / fmaxf(sqrtf(ss), 1e-12f);
    float4 en = make_float4(a.x * inv, a.y * inv, a.z * inv, a.w * inv);
    *(float4*)&g_ecur[(size_t)row * DD + lane * 4] = en;
    float4* es = (float4*)&g_esum[(size_t)row * DD + lane * 4];
    float4 o = *es;
    *es = make_float4(o.x + en.x, o.y + en.y, o.z + en.z, o.w + en.w);
}

// ---- final: scale user sums, write entity means ----
__global__ void k_final(float* __restrict__ out) {
    int i = blockIdx.x * blockDim.x + threadIdx.x;
    const float th = 1.f / 3.f;
    if (i < N_ENT * DD / 4) {
        float4 v = ((float4*)g_esum)[i];
        float4* oe = (float4*)(out + (size_t)N_USR * DD);
        oe[i] = make_float4(v.x * th, v.y * th, v.z * th, v.w * th);
    }
    if (i < N_USR * DD / 4) {
        float4* uo = (float4*)out;
        float4 v = uo[i];
        uo[i] = make_float4(v.x * th, v.y * th, v.z * th, v.w * th);
    }
}

extern "C" void kernel_launch(void* const* d_in, const int* in_sizes, int n_in,
                              void* d_out, int out_size) {
    // inputs (metadata order): layers_num, user_emb, entity_emb, inter_edge,
    // inter_edge_w, edge_index, edge_type, relation_emb, W_Q
    const float* user_emb = (const float*)d_in[1];
    const float* ent_emb  = (const float*)d_in[2];
    const int*   inter    = (const int*)d_in[3];
    const float* iw       = (const float*)d_in[4];
    const int*   eidx     = (const int*)d_in[5];
    const int*   etype    = (const int*)d_in[6];
    const float* rel      = (const float*)d_in[7];
    const float* WQ       = (const float*)d_in[8];
    const int* head = eidx;
    const int* tail = eidx + NE;
    const int* iu = inter;
    const int* ii = inter + NEI;
    float* out = (float*)d_out;

    const int T = 256;
    const int nE4 = N_ENT * DD / 4;  // 1.6M

    k_init<<<(nE4 + T - 1) / T, T>>>((const float4*)user_emb, (const float4*)ent_emb,
                                     (float4*)out);
    for (int l = 0; l < 2; l++) {
        k_gemm<<<N_ENT / 32, 256>>>(WQ);
        k_edge<<<(NE * 16 + T - 1) / T, T>>>(head, tail, etype, rel);
        k_user<<<(NEI * 16 + T - 1) / T, T>>>(iu, ii, iw, out);   // pre-update ecur
        k_update<<<(N_ENT * 16 + T - 1) / T, T>>>();
    }
    k_final<<<(nE4 + T - 1) / T, T>>>(out);
}